// round 3
// baseline (speedup 1.0000x reference)
#include <cuda_runtime.h>
#include <math.h>

#define NPTS 8192
#define KNN  10

__device__ float4 g_pts[NPTS];
__device__ int    g_nbr[NPTS * KNN];
__device__ float4 g_nrm[NPTS];
__device__ float  g_feats[NPTS * 8];
__device__ float  g_y0[NPTS * 32];
__device__ float  g_y1[NPTS * 64];
__device__ float  g_y2[NPTS * 128];
__device__ float  g_mean[128];
__device__ float  g_var[128];

// ---------------- LAPACK ssteqr mimic (double, fp32 thresholds) ----------------
__device__ __forceinline__ double dsign_(double a, double b) {
    return b >= 0.0 ? fabs(a) : -fabs(a);
}
__device__ __forceinline__ double lapy2_(double x, double y) {
    double ax = fabs(x), ay = fabs(y);
    double w = ax > ay ? ax : ay, z = ax > ay ? ay : ax;
    if (z == 0.0) return w;
    double q = z / w;
    return w * sqrt(1.0 + q * q);
}

__device__ void laev2_(double a, double b, double c,
                       double* rt1, double* rt2, double* cs1, double* sn1) {
    double sm = a + c, df = a - c, adf = fabs(df);
    double tb = b + b, ab = fabs(tb);
    double acmx, acmn;
    if (fabs(a) > fabs(c)) { acmx = a; acmn = c; } else { acmx = c; acmn = a; }
    double rt;
    if (adf > ab)      { double q = ab / adf; rt = adf * sqrt(1.0 + q * q); }
    else if (adf < ab) { double q = adf / ab; rt = ab * sqrt(1.0 + q * q); }
    else               { rt = ab * sqrt(2.0); }
    int sgn1;
    if (sm < 0.0)      { *rt1 = 0.5 * (sm - rt); sgn1 = -1; *rt2 = (acmx / *rt1) * acmn - (b / *rt1) * b; }
    else if (sm > 0.0) { *rt1 = 0.5 * (sm + rt); sgn1 =  1; *rt2 = (acmx / *rt1) * acmn - (b / *rt1) * b; }
    else               { *rt1 = 0.5 * rt; *rt2 = -0.5 * rt; sgn1 = 1; }
    double cs; int sgn2;
    if (df >= 0.0) { cs = df + rt; sgn2 = 1; } else { cs = df - rt; sgn2 = -1; }
    double acs = fabs(cs), c1, s1;
    if (acs > ab) {
        double ct = -tb / cs;
        s1 = 1.0 / sqrt(1.0 + ct * ct); c1 = ct * s1;
    } else {
        if (ab == 0.0) { c1 = 1.0; s1 = 0.0; }
        else { double tn = -cs / tb; c1 = 1.0 / sqrt(1.0 + tn * tn); s1 = tn * c1; }
    }
    if (sgn1 == sgn2) { double t = c1; c1 = -s1; s1 = t; }
    *cs1 = c1; *sn1 = s1;
}

// modern (>=3.10) slartg convention
__device__ void lartg_(double f, double g, double* cs, double* sn, double* r) {
    if (g == 0.0)      { *cs = 1.0; *sn = 0.0; *r = f; }
    else if (f == 0.0) { *cs = 0.0; *sn = (g >= 0.0) ? 1.0 : -1.0; *r = fabs(g); }
    else {
        double d = sqrt(f * f + g * g);
        *cs = fabs(f) / d;
        *r = (f >= 0.0) ? d : -d;
        *sn = g / *r;
    }
}

__device__ void steqr3_(double d[3], double e[2], double z[3][3]) {
    const double eps = 5.9604644775390625e-08;   // fp32 2^-24
    const double eps2 = eps * eps;
    const double safmin = 1.1754943508222875e-38;
    const int n = 3;
    for (int i = 0; i < 3; i++)
        for (int j = 0; j < 3; j++) z[i][j] = (i == j) ? 1.0 : 0.0;
    int nmaxit = n * 30, jtot = 0, l1 = 1;
    while (1) {
        if (l1 > n) break;
        if (l1 > 1) e[l1 - 2] = 0.0;
        int m = n;
        for (int mm = l1; mm <= n - 1; mm++) {
            double tst = fabs(e[mm - 1]);
            if (tst == 0.0) { m = mm; break; }
            if (tst <= (sqrt(fabs(d[mm - 1])) * sqrt(fabs(d[mm]))) * eps) {
                e[mm - 1] = 0.0; m = mm; break;
            }
        }
        int l = l1, lsv = l, lend = m, lendsv = lend;
        l1 = m + 1;
        if (lend == l) continue;
        double anorm = 0.0;
        for (int i = l; i <= lend; i++) anorm = fmax(anorm, fabs(d[i - 1]));
        for (int i = l; i <  lend; i++) anorm = fmax(anorm, fabs(e[i - 1]));
        if (anorm == 0.0) continue;
        if (fabs(d[lend - 1]) < fabs(d[l - 1])) { lend = lsv; l = lendsv; }
        if (lend > l) {
            // QL
            for (;;) {
                if (l != lend) {
                    m = lend;
                    for (int mm = l; mm <= lend - 1; mm++) {
                        double tst = e[mm - 1] * e[mm - 1];
                        if (tst <= (eps2 * fabs(d[mm - 1])) * fabs(d[mm]) + safmin) { m = mm; break; }
                    }
                } else m = l;
                if (m < lend) e[m - 1] = 0.0;
                double p = d[l - 1];
                if (m == l) { d[l - 1] = p; l++; if (l <= lend) continue; break; }
                if (m == l + 1) {
                    double rt1, rt2, c, s;
                    laev2_(d[l - 1], e[l - 1], d[l], &rt1, &rt2, &c, &s);
                    for (int i = 0; i < 3; i++) {
                        double t = z[i][l];
                        z[i][l]     = c * t - s * z[i][l - 1];
                        z[i][l - 1] = s * t + c * z[i][l - 1];
                    }
                    d[l - 1] = rt1; d[l] = rt2; e[l - 1] = 0.0;
                    l += 2; if (l <= lend) continue; break;
                }
                if (jtot == nmaxit) break;
                jtot++;
                double g = (d[l] - p) / (2.0 * e[l - 1]);
                double r = lapy2_(g, 1.0);
                g = d[m - 1] - p + e[l - 1] / (g + dsign_(r, g));
                double s = 1.0, c = 1.0; p = 0.0;
                double svc[2], svs[2];
                for (int i = m - 1; i >= l; i--) {
                    double f = s * e[i - 1], b = c * e[i - 1];
                    lartg_(g, f, &c, &s, &r);
                    if (i != m - 1) e[i] = r;
                    g = d[i] - p;
                    r = (d[i - 1] - g) * s + 2.0 * c * b;
                    p = s * r;
                    d[i] = g + p;
                    g = c * r - b;
                    svc[i - 1] = c; svs[i - 1] = -s;
                }
                for (int j = m - 1; j >= l; j--) {
                    double cj = svc[j - 1], sj = svs[j - 1];
                    for (int i = 0; i < 3; i++) {
                        double t = z[i][j];
                        z[i][j]     = cj * t - sj * z[i][j - 1];
                        z[i][j - 1] = sj * t + cj * z[i][j - 1];
                    }
                }
                d[l - 1] -= p; e[l - 1] = g;
            }
        } else {
            // QR
            for (;;) {
                if (l != lend) {
                    m = lend;
                    for (int mm = l; mm >= lend + 1; mm--) {
                        double tst = e[mm - 2] * e[mm - 2];
                        if (tst <= (eps2 * fabs(d[mm - 1])) * fabs(d[mm - 2]) + safmin) { m = mm; break; }
                    }
                } else m = l;
                if (m > lend) e[m - 2] = 0.0;
                double p = d[l - 1];
                if (m == l) { d[l - 1] = p; l--; if (l >= lend) continue; break; }
                if (m == l - 1) {
                    double rt1, rt2, c, s;
                    laev2_(d[l - 2], e[l - 2], d[l - 1], &rt1, &rt2, &c, &s);
                    for (int i = 0; i < 3; i++) {
                        double t = z[i][l - 1];
                        z[i][l - 1] = c * t - s * z[i][l - 2];
                        z[i][l - 2] = s * t + c * z[i][l - 2];
                    }
                    d[l - 2] = rt1; d[l - 1] = rt2; e[l - 2] = 0.0;
                    l -= 2; if (l >= lend) continue; break;
                }
                if (jtot == nmaxit) break;
                jtot++;
                double g = (d[l - 2] - p) / (2.0 * e[l - 2]);
                double r = lapy2_(g, 1.0);
                g = d[m - 1] - p + e[l - 2] / (g + dsign_(r, g));
                double s = 1.0, c = 1.0; p = 0.0;
                double svc[2], svs[2];
                for (int i = m; i <= l - 1; i++) {
                    double f = s * e[i - 1], b = c * e[i - 1];
                    lartg_(g, f, &c, &s, &r);
                    if (i != m) e[i - 2] = r;
                    g = d[i - 1] - p;
                    r = (d[i] - g) * s + 2.0 * c * b;
                    p = s * r;
                    d[i - 1] = g + p;
                    g = c * r - b;
                    svc[i - 1] = c; svs[i - 1] = s;
                }
                for (int j = m; j <= l - 1; j++) {
                    double cj = svc[j - 1], sj = svs[j - 1];
                    for (int i = 0; i < 3; i++) {
                        double t = z[i][j];
                        z[i][j]     = cj * t - sj * z[i][j - 1];
                        z[i][j - 1] = sj * t + cj * z[i][j - 1];
                    }
                }
                d[l - 1] -= p; e[l - 2] = g;
            }
        }
        if (jtot >= nmaxit) break;
    }
    // ascending selection sort (LAPACK step 160)
    for (int ii = 2; ii <= 3; ii++) {
        int i = ii - 1, k = i;
        double p = d[i - 1];
        for (int j = ii; j <= 3; j++) if (d[j - 1] < p) { k = j; p = d[j - 1]; }
        if (k != i) {
            d[k - 1] = d[i - 1]; d[i - 1] = p;
            for (int r2 = 0; r2 < 3; r2++) {
                double t = z[r2][i - 1]; z[r2][i - 1] = z[r2][k - 1]; z[r2][k - 1] = t;
            }
        }
    }
}

// ---------------- kernels ----------------
__global__ void prep_kernel(const float* __restrict__ voxels) {
    int i = blockIdx.x * blockDim.x + threadIdx.x;
    if (i >= NPTS) return;
    float x = voxels[3 * i], y = voxels[3 * i + 1], z = voxels[3 * i + 2];
    g_pts[i] = make_float4(x, y, z, x * x + y * y + z * z);
}

__global__ void knn_kernel() {
    __shared__ float4 tile[256];
    int i = blockIdx.x * 256 + threadIdx.x;
    float4 q = g_pts[i];
    float dk[KNN]; int ik[KNN];
#pragma unroll
    for (int k = 0; k < KNN; k++) { dk[k] = 3.4e38f; ik[k] = 0; }
    for (int t = 0; t < NPTS / 256; t++) {
        __syncthreads();
        tile[threadIdx.x] = g_pts[t * 256 + threadIdx.x];
        __syncthreads();
#pragma unroll 4
        for (int jj = 0; jj < 256; jj++) {
            int j = t * 256 + jj;
            float4 p = tile[jj];
            float dot = fmaf(q.x, p.x, fmaf(q.y, p.y, q.z * p.z));
            float d2 = (q.w + p.w) - 2.0f * dot;
            if (d2 < dk[KNN - 1] && j != i) {
                float cd = d2; int ci = j;
#pragma unroll
                for (int k = 0; k < KNN; k++) {
                    if (cd < dk[k]) {
                        float td = dk[k]; int ti = ik[k];
                        dk[k] = cd; ik[k] = ci;
                        cd = td; ci = ti;
                    }
                }
            }
        }
    }
#pragma unroll
    for (int k = 0; k < KNN; k++) g_nbr[i * KNN + k] = ik[k];
}

__global__ void normals_kernel() {
    int i = blockIdx.x * blockDim.x + threadIdx.x;
    if (i >= NPTS) return;
    float4 c = g_pts[i];
    float sxx = 0, sxy = 0, sxz = 0, syy = 0, syz = 0, szz = 0;
    for (int k = 0; k < KNN; k++) {
        float4 p = g_pts[g_nbr[i * KNN + k]];
        float lx = p.x - c.x, ly = p.y - c.y, lz = p.z - c.z;
        sxx += lx * lx; sxy += lx * ly; sxz += lx * lz;
        syy += ly * ly; syz += ly * lz; szz += lz * lz;
    }
    float inv9 = 1.0f / 9.0f;
    double a11 = sxx * inv9, a21 = sxy * inv9, a31 = sxz * inv9;
    double a22 = syy * inv9, a32 = syz * inv9, a33 = szz * inv9;
    // ssytd2 (lower, n=3): one reflector annihilating a31
    double tau = 0.0, v2 = 0.0, e0, d1 = a11, d2 = a22, d3 = a33, e1 = a32;
    if (a31 == 0.0) {
        e0 = a21;
    } else {
        double alpha = a21, xnorm = fabs(a31);
        double beta = -dsign_(lapy2_(alpha, xnorm), alpha);
        tau = (beta - alpha) / beta;
        v2 = a31 / (alpha - beta);
        e0 = beta;
        // trailing 2x2 update: A22 -= v w^T + w v^T, v = (1, v2)
        double x1 = tau * (a22 + a32 * v2);
        double x2 = tau * (a32 + a33 * v2);
        double ac = -0.5 * tau * (x1 + x2 * v2);
        double w1 = x1 + ac, w2 = x2 + ac * v2;
        d2 = a22 - 2.0 * w1;
        e1 = a32 - (v2 * w1 + w2);
        d3 = a33 - 2.0 * v2 * w2;
    }
    double dd[3] = {d1, d2, d3};
    double ee[2] = {e0, e1};
    double z[3][3];
    steqr3_(dd, ee, z);
    // sormtr: apply H = I - tau v v^T to rows 2..3 of Z
    if (tau != 0.0) {
        for (int jc = 0; jc < 3; jc++) {
            double s = tau * (z[1][jc] + v2 * z[2][jc]);
            z[1][jc] -= s;
            z[2][jc] -= s * v2;
        }
    }
    float nx = (float)z[0][0], ny = (float)z[1][0], nz = (float)z[2][0];
    float nrm = sqrtf(nx * nx + ny * ny + nz * nz);
    float inv = 1.0f / fmaxf(nrm, 1e-12f);
    g_nrm[i] = make_float4(nx * inv, ny * inv, nz * inv, 0.0f);
}

__global__ void feats_kernel() {
    int i = blockIdx.x * blockDim.x + threadIdx.x;
    if (i >= NPTS) return;
    float4 n = g_nrm[i];
    float s = 0.0f;
    for (int k = 0; k < KNN; k++) {
        float4 m = g_nrm[g_nbr[i * KNN + k]];
        float dx = m.x - n.x, dy = m.y - n.y, dz = m.z - n.z;
        s += sqrtf(dx * dx + dy * dy + dz * dz);
    }
    float4 p = g_pts[i];
    float* f = g_feats + i * 8;
    f[0] = p.x; f[1] = p.y; f[2] = p.z;
    f[3] = n.x; f[4] = n.y; f[5] = n.z;
    f[6] = s / (float)KNN;
    f[7] = sqrtf(p.w);
}

template<int CIN, int COUT, bool BN_IN, bool BIAS>
__global__ void gemm_kernel(const float* __restrict__ X, const float* __restrict__ W,
                            const float* __restrict__ bias, const float* __restrict__ gam,
                            const float* __restrict__ bet, float* __restrict__ Y) {
    __shared__ float sx[CIN];
    int r = blockIdx.x, c = threadIdx.x;
    for (int k = c; k < CIN; k += COUT) {
        float v = X[r * CIN + k];
        if (BN_IN) {
            float inv = 1.0f / sqrtf(g_var[k] + 1e-5f);
            v = gam[k] * (v - g_mean[k]) * inv + bet[k];
            v = fmaxf(v, 0.0f);   // relu
        }
        sx[k] = v;
    }
    __syncthreads();
    float s = 0.0f;
#pragma unroll
    for (int k = 0; k < CIN; k++) s = fmaf(sx[k], W[k * COUT + c], s);
    if (BIAS) s += bias[c];
    Y[r * COUT + c] = s;
}

template<int COUT>
__global__ void stats_kernel(const float* __restrict__ Y) {
    __shared__ double ss[256], ss2[256];
    int c = blockIdx.x, t = threadIdx.x;
    double s = 0.0, s2 = 0.0;
    for (int r = t; r < NPTS; r += 256) {
        double v = (double)Y[r * COUT + c];
        s += v; s2 += v * v;
    }
    ss[t] = s; ss2[t] = s2;
    __syncthreads();
    for (int o = 128; o > 0; o >>= 1) {
        if (t < o) { ss[t] += ss[t + o]; ss2[t] += ss2[t + o]; }
        __syncthreads();
    }
    if (t == 0) {
        double m = ss[0] / (double)NPTS;
        g_mean[c] = (float)m;
        g_var[c] = (float)(ss2[0] / (double)NPTS - m * m);
    }
}

__global__ void bnout_kernel(const float* __restrict__ Y, const float* __restrict__ gam,
                             const float* __restrict__ bet, float* __restrict__ out) {
    int r = blockIdx.x, c = threadIdx.x;
    float inv = 1.0f / sqrtf(g_var[c] + 1e-5f);
    out[r * 128 + c] = gam[c] * (Y[r * 128 + c] - g_mean[c]) * inv + bet[c];
}

extern "C" void kernel_launch(void* const* d_in, const int* in_sizes, int n_in,
                              void* d_out, int out_size) {
    const float* voxels = (const float*)d_in[0];
    const float* W0 = (const float*)d_in[1];
    const float* g0 = (const float*)d_in[2];
    const float* b0 = (const float*)d_in[3];
    const float* W1 = (const float*)d_in[4];
    const float* g1 = (const float*)d_in[5];
    const float* b1 = (const float*)d_in[6];
    const float* W2 = (const float*)d_in[7];
    const float* bias2 = (const float*)d_in[8];
    const float* g2 = (const float*)d_in[9];
    const float* b2 = (const float*)d_in[10];
    float* out = (float*)d_out;

    float *y0, *y1, *y2, *feats;
    cudaGetSymbolAddress((void**)&y0, g_y0);
    cudaGetSymbolAddress((void**)&y1, g_y1);
    cudaGetSymbolAddress((void**)&y2, g_y2);
    cudaGetSymbolAddress((void**)&feats, g_feats);

    prep_kernel<<<NPTS / 256, 256>>>(voxels);
    knn_kernel<<<NPTS / 256, 256>>>();
    normals_kernel<<<NPTS / 128, 128>>>();
    feats_kernel<<<NPTS / 256, 256>>>();
    gemm_kernel<8, 32, false, false><<<NPTS, 32>>>(feats, W0, nullptr, nullptr, nullptr, y0);
    stats_kernel<32><<<32, 256>>>(y0);
    gemm_kernel<32, 64, true, false><<<NPTS, 64>>>(y0, W1, nullptr, g0, b0, y1);
    stats_kernel<64><<<64, 256>>>(y1);
    gemm_kernel<64, 128, true, true><<<NPTS, 128>>>(y1, W2, bias2, g1, b1, y2);
    stats_kernel<128><<<128, 256>>>(y2);
    bnout_kernel<<<NPTS, 128>>>(y2, g2, b2, out);
}

// round 4
// speedup vs baseline: 1.8949x; 1.8949x over previous
#include <cuda_runtime.h>
#include <math.h>

#define NPTS 8192
#define KNN  10
#define SEG  16
#define SEGLEN (NPTS / SEG)   // 512

__device__ float4 g_pts[NPTS];
__device__ int    g_nbr[NPTS * KNN];
__device__ float  g_cd[NPTS * SEG * KNN];
__device__ int    g_ci[NPTS * SEG * KNN];
__device__ float4 g_nrm[NPTS];
__device__ float  g_feats[NPTS * 8];
__device__ float  g_y0[NPTS * 32];
__device__ float  g_y1[NPTS * 64];
__device__ float  g_y2[NPTS * 128];
__device__ float  g_mean[128];
__device__ float  g_var[128];

// ---------------- LAPACK ssteqr mimic (double, fp32 thresholds) ----------------
__device__ __forceinline__ double dsign_(double a, double b) {
    return b >= 0.0 ? fabs(a) : -fabs(a);
}
__device__ __forceinline__ double lapy2_(double x, double y) {
    double ax = fabs(x), ay = fabs(y);
    double w = ax > ay ? ax : ay, z = ax > ay ? ay : ax;
    if (z == 0.0) return w;
    double q = z / w;
    return w * sqrt(1.0 + q * q);
}

__device__ void laev2_(double a, double b, double c,
                       double* rt1, double* rt2, double* cs1, double* sn1) {
    double sm = a + c, df = a - c, adf = fabs(df);
    double tb = b + b, ab = fabs(tb);
    double acmx, acmn;
    if (fabs(a) > fabs(c)) { acmx = a; acmn = c; } else { acmx = c; acmn = a; }
    double rt;
    if (adf > ab)      { double q = ab / adf; rt = adf * sqrt(1.0 + q * q); }
    else if (adf < ab) { double q = adf / ab; rt = ab * sqrt(1.0 + q * q); }
    else               { rt = ab * sqrt(2.0); }
    int sgn1;
    if (sm < 0.0)      { *rt1 = 0.5 * (sm - rt); sgn1 = -1; *rt2 = (acmx / *rt1) * acmn - (b / *rt1) * b; }
    else if (sm > 0.0) { *rt1 = 0.5 * (sm + rt); sgn1 =  1; *rt2 = (acmx / *rt1) * acmn - (b / *rt1) * b; }
    else               { *rt1 = 0.5 * rt; *rt2 = -0.5 * rt; sgn1 = 1; }
    double cs; int sgn2;
    if (df >= 0.0) { cs = df + rt; sgn2 = 1; } else { cs = df - rt; sgn2 = -1; }
    double acs = fabs(cs), c1, s1;
    if (acs > ab) {
        double ct = -tb / cs;
        s1 = 1.0 / sqrt(1.0 + ct * ct); c1 = ct * s1;
    } else {
        if (ab == 0.0) { c1 = 1.0; s1 = 0.0; }
        else { double tn = -cs / tb; c1 = 1.0 / sqrt(1.0 + tn * tn); s1 = tn * c1; }
    }
    if (sgn1 == sgn2) { double t = c1; c1 = -s1; s1 = t; }
    *cs1 = c1; *sn1 = s1;
}

__device__ void lartg_(double f, double g, double* cs, double* sn, double* r) {
    if (g == 0.0)      { *cs = 1.0; *sn = 0.0; *r = f; }
    else if (f == 0.0) { *cs = 0.0; *sn = (g >= 0.0) ? 1.0 : -1.0; *r = fabs(g); }
    else {
        double d = sqrt(f * f + g * g);
        *cs = fabs(f) / d;
        *r = (f >= 0.0) ? d : -d;
        *sn = g / *r;
    }
}

__device__ void steqr3_(double d[3], double e[2], double z[3][3]) {
    const double eps = 5.9604644775390625e-08;   // fp32 2^-24
    const double eps2 = eps * eps;
    const double safmin = 1.1754943508222875e-38;
    const int n = 3;
    for (int i = 0; i < 3; i++)
        for (int j = 0; j < 3; j++) z[i][j] = (i == j) ? 1.0 : 0.0;
    int nmaxit = n * 30, jtot = 0, l1 = 1;
    while (1) {
        if (l1 > n) break;
        if (l1 > 1) e[l1 - 2] = 0.0;
        int m = n;
        for (int mm = l1; mm <= n - 1; mm++) {
            double tst = fabs(e[mm - 1]);
            if (tst == 0.0) { m = mm; break; }
            if (tst <= (sqrt(fabs(d[mm - 1])) * sqrt(fabs(d[mm]))) * eps) {
                e[mm - 1] = 0.0; m = mm; break;
            }
        }
        int l = l1, lsv = l, lend = m, lendsv = lend;
        l1 = m + 1;
        if (lend == l) continue;
        double anorm = 0.0;
        for (int i = l; i <= lend; i++) anorm = fmax(anorm, fabs(d[i - 1]));
        for (int i = l; i <  lend; i++) anorm = fmax(anorm, fabs(e[i - 1]));
        if (anorm == 0.0) continue;
        if (fabs(d[lend - 1]) < fabs(d[l - 1])) { lend = lsv; l = lendsv; }
        if (lend > l) {
            for (;;) {   // QL
                if (l != lend) {
                    m = lend;
                    for (int mm = l; mm <= lend - 1; mm++) {
                        double tst = e[mm - 1] * e[mm - 1];
                        if (tst <= (eps2 * fabs(d[mm - 1])) * fabs(d[mm]) + safmin) { m = mm; break; }
                    }
                } else m = l;
                if (m < lend) e[m - 1] = 0.0;
                double p = d[l - 1];
                if (m == l) { d[l - 1] = p; l++; if (l <= lend) continue; break; }
                if (m == l + 1) {
                    double rt1, rt2, c, s;
                    laev2_(d[l - 1], e[l - 1], d[l], &rt1, &rt2, &c, &s);
                    for (int i = 0; i < 3; i++) {
                        double t = z[i][l];
                        z[i][l]     = c * t - s * z[i][l - 1];
                        z[i][l - 1] = s * t + c * z[i][l - 1];
                    }
                    d[l - 1] = rt1; d[l] = rt2; e[l - 1] = 0.0;
                    l += 2; if (l <= lend) continue; break;
                }
                if (jtot == nmaxit) break;
                jtot++;
                double g = (d[l] - p) / (2.0 * e[l - 1]);
                double r = lapy2_(g, 1.0);
                g = d[m - 1] - p + e[l - 1] / (g + dsign_(r, g));
                double s = 1.0, c = 1.0; p = 0.0;
                double svc[2], svs[2];
                for (int i = m - 1; i >= l; i--) {
                    double f = s * e[i - 1], b = c * e[i - 1];
                    lartg_(g, f, &c, &s, &r);
                    if (i != m - 1) e[i] = r;
                    g = d[i] - p;
                    r = (d[i - 1] - g) * s + 2.0 * c * b;
                    p = s * r;
                    d[i] = g + p;
                    g = c * r - b;
                    svc[i - 1] = c; svs[i - 1] = -s;
                }
                for (int j = m - 1; j >= l; j--) {
                    double cj = svc[j - 1], sj = svs[j - 1];
                    for (int i = 0; i < 3; i++) {
                        double t = z[i][j];
                        z[i][j]     = cj * t - sj * z[i][j - 1];
                        z[i][j - 1] = sj * t + cj * z[i][j - 1];
                    }
                }
                d[l - 1] -= p; e[l - 1] = g;
            }
        } else {
            for (;;) {   // QR
                if (l != lend) {
                    m = lend;
                    for (int mm = l; mm >= lend + 1; mm--) {
                        double tst = e[mm - 2] * e[mm - 2];
                        if (tst <= (eps2 * fabs(d[mm - 1])) * fabs(d[mm - 2]) + safmin) { m = mm; break; }
                    }
                } else m = l;
                if (m > lend) e[m - 2] = 0.0;
                double p = d[l - 1];
                if (m == l) { d[l - 1] = p; l--; if (l >= lend) continue; break; }
                if (m == l - 1) {
                    double rt1, rt2, c, s;
                    laev2_(d[l - 2], e[l - 2], d[l - 1], &rt1, &rt2, &c, &s);
                    for (int i = 0; i < 3; i++) {
                        double t = z[i][l - 1];
                        z[i][l - 1] = c * t - s * z[i][l - 2];
                        z[i][l - 2] = s * t + c * z[i][l - 2];
                    }
                    d[l - 2] = rt1; d[l - 1] = rt2; e[l - 2] = 0.0;
                    l -= 2; if (l >= lend) continue; break;
                }
                if (jtot == nmaxit) break;
                jtot++;
                double g = (d[l - 2] - p) / (2.0 * e[l - 2]);
                double r = lapy2_(g, 1.0);
                g = d[m - 1] - p + e[l - 2] / (g + dsign_(r, g));
                double s = 1.0, c = 1.0; p = 0.0;
                double svc[2], svs[2];
                for (int i = m; i <= l - 1; i++) {
                    double f = s * e[i - 1], b = c * e[i - 1];
                    lartg_(g, f, &c, &s, &r);
                    if (i != m) e[i - 2] = r;
                    g = d[i - 1] - p;
                    r = (d[i] - g) * s + 2.0 * c * b;
                    p = s * r;
                    d[i - 1] = g + p;
                    g = c * r - b;
                    svc[i - 1] = c; svs[i - 1] = s;
                }
                for (int j = m; j <= l - 1; j++) {
                    double cj = svc[j - 1], sj = svs[j - 1];
                    for (int i = 0; i < 3; i++) {
                        double t = z[i][j];
                        z[i][j]     = cj * t - sj * z[i][j - 1];
                        z[i][j - 1] = sj * t + cj * z[i][j - 1];
                    }
                }
                d[l - 1] -= p; e[l - 2] = g;
            }
        }
        if (jtot >= nmaxit) break;
    }
    for (int ii = 2; ii <= 3; ii++) {
        int i = ii - 1, k = i;
        double p = d[i - 1];
        for (int j = ii; j <= 3; j++) if (d[j - 1] < p) { k = j; p = d[j - 1]; }
        if (k != i) {
            d[k - 1] = d[i - 1]; d[i - 1] = p;
            for (int r2 = 0; r2 < 3; r2++) {
                double t = z[r2][i - 1]; z[r2][i - 1] = z[r2][k - 1]; z[r2][k - 1] = t;
            }
        }
    }
}

// ---------------- kernels ----------------
__global__ void prep_kernel(const float* __restrict__ voxels) {
    int i = blockIdx.x * blockDim.x + threadIdx.x;
    if (i >= NPTS) return;
    float x = voxels[3 * i], y = voxels[3 * i + 1], z = voxels[3 * i + 2];
    g_pts[i] = make_float4(x, y, z, x * x + y * y + z * z);
}

// Partial KNN: each block handles one (point-block, segment) pair.
__global__ void knn_part_kernel() {
    __shared__ float4 tile[SEGLEN];
    int pb = blockIdx.x / SEG;
    int s  = blockIdx.x % SEG;
    int i  = pb * 256 + threadIdx.x;
    float4 q = g_pts[i];
    for (int t = threadIdx.x; t < SEGLEN; t += 256)
        tile[t] = g_pts[s * SEGLEN + t];
    __syncthreads();
    float dk[KNN]; int ik[KNN];
#pragma unroll
    for (int k = 0; k < KNN; k++) { dk[k] = 3.4e38f; ik[k] = 0; }
    int jbase = s * SEGLEN;
#pragma unroll 4
    for (int jj = 0; jj < SEGLEN; jj++) {
        float4 p = tile[jj];
        float dot = fmaf(q.x, p.x, fmaf(q.y, p.y, q.z * p.z));
        float d2 = (q.w + p.w) - 2.0f * dot;     // identical expr to passing kernel
        int j = jbase + jj;
        if (d2 < dk[KNN - 1] && j != i) {
            float cd = d2; int ci = j;
#pragma unroll
            for (int k = 0; k < KNN; k++) {
                if (cd < dk[k]) {
                    float td = dk[k]; int ti = ik[k];
                    dk[k] = cd; ik[k] = ci;
                    cd = td; ci = ti;
                }
            }
        }
    }
    int base = (i * SEG + s) * KNN;
#pragma unroll
    for (int k = 0; k < KNN; k++) { g_cd[base + k] = dk[k]; g_ci[base + k] = ik[k]; }
}

// Merge SEG sorted partial top-10 lists per point; segments ascending keeps
// the j-ascending tie order, so strict-< insertion == top_k tie-break.
__global__ void knn_merge_kernel() {
    int i = blockIdx.x * blockDim.x + threadIdx.x;
    if (i >= NPTS) return;
    float dk[KNN]; int ik[KNN];
#pragma unroll
    for (int k = 0; k < KNN; k++) { dk[k] = 3.4e38f; ik[k] = 0; }
    for (int s = 0; s < SEG; s++) {
        int base = (i * SEG + s) * KNN;
#pragma unroll
        for (int k = 0; k < KNN; k++) {
            float cd = g_cd[base + k];
            if (!(cd < dk[KNN - 1])) break;   // segment list sorted ascending
            int ci = g_ci[base + k];
#pragma unroll
            for (int kk = 0; kk < KNN; kk++) {
                if (cd < dk[kk]) {
                    float td = dk[kk]; int ti = ik[kk];
                    dk[kk] = cd; ik[kk] = ci;
                    cd = td; ci = ti;
                }
            }
        }
    }
#pragma unroll
    for (int k = 0; k < KNN; k++) g_nbr[i * KNN + k] = ik[k];
}

__global__ void normals_kernel() {
    int i = blockIdx.x * blockDim.x + threadIdx.x;
    if (i >= NPTS) return;
    float4 c = g_pts[i];
    float sxx = 0, sxy = 0, sxz = 0, syy = 0, syz = 0, szz = 0;
    for (int k = 0; k < KNN; k++) {
        float4 p = g_pts[g_nbr[i * KNN + k]];
        float lx = p.x - c.x, ly = p.y - c.y, lz = p.z - c.z;
        sxx += lx * lx; sxy += lx * ly; sxz += lx * lz;
        syy += ly * ly; syz += ly * lz; szz += lz * lz;
    }
    float inv9 = 1.0f / 9.0f;
    double a11 = sxx * inv9, a21 = sxy * inv9, a31 = sxz * inv9;
    double a22 = syy * inv9, a32 = syz * inv9, a33 = szz * inv9;
    double tau = 0.0, v2 = 0.0, e0, d1 = a11, d2 = a22, d3 = a33, e1 = a32;
    if (a31 == 0.0) {
        e0 = a21;
    } else {
        double alpha = a21, xnorm = fabs(a31);
        double beta = -dsign_(lapy2_(alpha, xnorm), alpha);
        tau = (beta - alpha) / beta;
        v2 = a31 / (alpha - beta);
        e0 = beta;
        double x1 = tau * (a22 + a32 * v2);
        double x2 = tau * (a32 + a33 * v2);
        double ac = -0.5 * tau * (x1 + x2 * v2);
        double w1 = x1 + ac, w2 = x2 + ac * v2;
        d2 = a22 - 2.0 * w1;
        e1 = a32 - (v2 * w1 + w2);
        d3 = a33 - 2.0 * v2 * w2;
    }
    double dd[3] = {d1, d2, d3};
    double ee[2] = {e0, e1};
    double z[3][3];
    steqr3_(dd, ee, z);
    if (tau != 0.0) {
        for (int jc = 0; jc < 3; jc++) {
            double s = tau * (z[1][jc] + v2 * z[2][jc]);
            z[1][jc] -= s;
            z[2][jc] -= s * v2;
        }
    }
    float nx = (float)z[0][0], ny = (float)z[1][0], nz = (float)z[2][0];
    float nrm = sqrtf(nx * nx + ny * ny + nz * nz);
    float inv = 1.0f / fmaxf(nrm, 1e-12f);
    g_nrm[i] = make_float4(nx * inv, ny * inv, nz * inv, 0.0f);
}

__global__ void feats_kernel() {
    int i = blockIdx.x * blockDim.x + threadIdx.x;
    if (i >= NPTS) return;
    float4 n = g_nrm[i];
    float s = 0.0f;
    for (int k = 0; k < KNN; k++) {
        float4 m = g_nrm[g_nbr[i * KNN + k]];
        float dx = m.x - n.x, dy = m.y - n.y, dz = m.z - n.z;
        s += sqrtf(dx * dx + dy * dy + dz * dz);
    }
    float4 p = g_pts[i];
    float* f = g_feats + i * 8;
    f[0] = p.x; f[1] = p.y; f[2] = p.z;
    f[3] = n.x; f[4] = n.y; f[5] = n.z;
    f[6] = s / (float)KNN;
    f[7] = sqrtf(p.w);
}

template<int CIN, int COUT, bool BN_IN, bool BIAS>
__global__ void gemm_kernel(const float* __restrict__ X, const float* __restrict__ W,
                            const float* __restrict__ bias, const float* __restrict__ gam,
                            const float* __restrict__ bet, float* __restrict__ Y) {
    __shared__ float sx[CIN];
    int r = blockIdx.x, c = threadIdx.x;
    for (int k = c; k < CIN; k += COUT) {
        float v = X[r * CIN + k];
        if (BN_IN) {
            float inv = 1.0f / sqrtf(g_var[k] + 1e-5f);
            v = gam[k] * (v - g_mean[k]) * inv + bet[k];
            v = fmaxf(v, 0.0f);
        }
        sx[k] = v;
    }
    __syncthreads();
    float s = 0.0f;
#pragma unroll
    for (int k = 0; k < CIN; k++) s = fmaf(sx[k], W[k * COUT + c], s);
    if (BIAS) s += bias[c];
    Y[r * COUT + c] = s;
}

template<int COUT>
__global__ void stats_kernel(const float* __restrict__ Y) {
    __shared__ double ss[256], ss2[256];
    int c = blockIdx.x, t = threadIdx.x;
    double s = 0.0, s2 = 0.0;
    for (int r = t; r < NPTS; r += 256) {
        double v = (double)Y[r * COUT + c];
        s += v; s2 += v * v;
    }
    ss[t] = s; ss2[t] = s2;
    __syncthreads();
    for (int o = 128; o > 0; o >>= 1) {
        if (t < o) { ss[t] += ss[t + o]; ss2[t] += ss2[t + o]; }
        __syncthreads();
    }
    if (t == 0) {
        double m = ss[0] / (double)NPTS;
        g_mean[c] = (float)m;
        g_var[c] = (float)(ss2[0] / (double)NPTS - m * m);
    }
}

__global__ void bnout_kernel(const float* __restrict__ Y, const float* __restrict__ gam,
                             const float* __restrict__ bet, float* __restrict__ out) {
    int r = blockIdx.x, c = threadIdx.x;
    float inv = 1.0f / sqrtf(g_var[c] + 1e-5f);
    out[r * 128 + c] = gam[c] * (Y[r * 128 + c] - g_mean[c]) * inv + bet[c];
}

extern "C" void kernel_launch(void* const* d_in, const int* in_sizes, int n_in,
                              void* d_out, int out_size) {
    const float* voxels = (const float*)d_in[0];
    const float* W0 = (const float*)d_in[1];
    const float* g0 = (const float*)d_in[2];
    const float* b0 = (const float*)d_in[3];
    const float* W1 = (const float*)d_in[4];
    const float* g1 = (const float*)d_in[5];
    const float* b1 = (const float*)d_in[6];
    const float* W2 = (const float*)d_in[7];
    const float* bias2 = (const float*)d_in[8];
    const float* g2 = (const float*)d_in[9];
    const float* b2 = (const float*)d_in[10];
    float* out = (float*)d_out;

    float *y0, *y1, *y2, *feats;
    cudaGetSymbolAddress((void**)&y0, g_y0);
    cudaGetSymbolAddress((void**)&y1, g_y1);
    cudaGetSymbolAddress((void**)&y2, g_y2);
    cudaGetSymbolAddress((void**)&feats, g_feats);

    prep_kernel<<<NPTS / 256, 256>>>(voxels);
    knn_part_kernel<<<(NPTS / 256) * SEG, 256>>>();
    knn_merge_kernel<<<NPTS / 256, 256>>>();
    normals_kernel<<<NPTS / 128, 128>>>();
    feats_kernel<<<NPTS / 256, 256>>>();
    gemm_kernel<8, 32, false, false><<<NPTS, 32>>>(feats, W0, nullptr, nullptr, nullptr, y0);
    stats_kernel<32><<<32, 256>>>(y0);
    gemm_kernel<32, 64, true, false><<<NPTS, 64>>>(y0, W1, nullptr, g0, b0, y1);
    stats_kernel<64><<<64, 256>>>(y1);
    gemm_kernel<64, 128, true, true><<<NPTS, 128>>>(y1, W2, bias2, g1, b1, y2);
    stats_kernel<128><<<128, 256>>>(y2);
    bnout_kernel<<<NPTS, 128>>>(y2, g2, b2, out);
}